// round 1
// baseline (speedup 1.0000x reference)
#include <cuda_runtime.h>
#include <cuda_bf16.h>
#include <math.h>

#define BB   2
#define LL   9216
#define HH   96
#define WIMG 96
#define D2C  192
#define D4C  768
#define NST  16
#define NCH  96   // number of scan chunks
#define CLEN 96   // chunk length  (NCH*CLEN == LL)

// ---------------- scratch (device globals; no allocation) ----------------
__device__ float g_xz   [BB*LL*384];       // (b,l,384): xx | z
__device__ float g_xc   [BB*LL*D2C];       // conv+silu output, (b,l,192)
__device__ float g_xdbl [BB*LL*40];        // dt[0:6) pad[6:8) B[8:24) C[24:40)
__device__ float g_delta[BB*LL*D4C];       // softplus deltas
__device__ float g_y    [BB*LL*D4C];       // scan outputs
__device__ float g_chH  [BB*NCH*D4C*NST];  // chunk local end-state -> then h0
__device__ float g_chP  [BB*NCH*D4C*NST];  // chunk a-products
__device__ float g_A    [D4C*NST];         // -exp(A_log)
__device__ float g_Wf   [D2C*38];          // folded forward W_x
__device__ float g_Wb   [D2C*38];          // folded backward W_x

// ---------------- prep: A table + folded W_x ----------------
__global__ void k_prep(const float* __restrict__ A_log, const float* __restrict__ W_x) {
    int i = blockIdx.x*256 + threadIdx.x;
    if (i < D4C*NST) g_A[i] = -expf(A_log[i]);
    if (i < D2C*38) {
        int d = i/38, j = i%38;
        g_Wf[i] = W_x[d*38+j]       + W_x[(d+192)*38+j];
        g_Wb[i] = W_x[(d+384)*38+j] + W_x[(d+576)*38+j];
    }
}

// ---------------- K1: in-projection GEMM (96 -> 384 per pixel) ----------------
// block: 512 threads, tile 64 pixels. eg = lane-ish e group, jq = pixel quad.
__global__ void k1_inproj(const float* __restrict__ x,
                          const float* __restrict__ W_in,
                          const float* __restrict__ b_in) {
    __shared__ float sX[24*64];
    __shared__ float sW[24*384];
    int tid = threadIdx.x;
    int b  = blockIdx.y;
    int l0 = blockIdx.x*64;
    int eg = tid & 31;       // 0..31
    int jq = tid >> 5;       // 0..15
    float4 acc[12];
#pragma unroll
    for (int ei = 0; ei < 12; ei++) acc[ei] = make_float4(0.f,0.f,0.f,0.f);

    for (int c0 = 0; c0 < 96; c0 += 24) {
        __syncthreads();
        for (int i = tid; i < 24*64; i += 512) {
            int c = i >> 6, j = i & 63;
            sX[i] = x[(b*96 + c0 + c)*LL + l0 + j];
        }
        for (int i = tid; i < 24*384; i += 512)
            sW[i] = W_in[c0*384 + i];
        __syncthreads();
#pragma unroll
        for (int cc = 0; cc < 24; cc++) {
            float4 xv = *(const float4*)(sX + cc*64 + jq*4);
#pragma unroll
            for (int ei = 0; ei < 12; ei++) {
                float w = sW[cc*384 + ei*32 + eg];
                acc[ei].x += xv.x*w; acc[ei].y += xv.y*w;
                acc[ei].z += xv.z*w; acc[ei].w += xv.w*w;
            }
        }
    }
    int lbase = l0 + jq*4;
#pragma unroll
    for (int ei = 0; ei < 12; ei++) {
        int e = ei*32 + eg;
        float bb = b_in[e];
        g_xz[(size_t)(b*LL + lbase+0)*384 + e] = acc[ei].x + bb;
        g_xz[(size_t)(b*LL + lbase+1)*384 + e] = acc[ei].y + bb;
        g_xz[(size_t)(b*LL + lbase+2)*384 + e] = acc[ei].z + bb;
        g_xz[(size_t)(b*LL + lbase+3)*384 + e] = acc[ei].w + bb;
    }
}

// ---------------- K2: depthwise 3x3 conv + bias + SiLU ----------------
__global__ void k2_conv(const float* __restrict__ w_dw, const float* __restrict__ b_dw) {
    int g = blockIdx.x*256 + threadIdx.x;          // < BB*LL*192
    int d = g % 192;
    int rem = g / 192;
    int l = rem % LL;
    int b = rem / LL;
    int h = l / WIMG, w = l % WIMG;
    float acc = b_dw[d];
#pragma unroll
    for (int kh = -1; kh <= 1; kh++) {
        int hh = h + kh;
        if (hh < 0 || hh >= HH) continue;
#pragma unroll
        for (int kw = -1; kw <= 1; kw++) {
            int ww = w + kw;
            if (ww < 0 || ww >= WIMG) continue;
            acc += g_xz[(size_t)(b*LL + hh*WIMG + ww)*384 + d]
                 * w_dw[d*9 + (kh+1)*3 + (kw+1)];
        }
    }
    float val = acc / (1.f + __expf(-acc));
    g_xc[(size_t)(b*LL + l)*192 + d] = val;
}

// ---------------- K3a: x_dbl = flat·Wf + flip·Wb  (-> dt, B, C) ----------------
// block: 320 threads = 8 l-rows x 40 (j<38 active)
__global__ void k3a_xdbl() {
    __shared__ float sXf[8*192];
    __shared__ float sXb[8*192];
    __shared__ float sWf[96*38];
    __shared__ float sWb[96*38];
    int tid = threadIdx.x;
    int li = tid / 40, j = tid % 40;

    for (int i = tid; i < 8*192; i += 320) {
        int li2 = i / 192, d = i % 192;
        int lg2 = blockIdx.x*8 + li2;
        int b2 = lg2 / LL, l2 = lg2 % LL;
        sXf[i] = g_xc[(size_t)(b2*LL + l2)*192 + d];
        sXb[i] = g_xc[(size_t)(b2*LL + (LL-1-l2))*192 + d];
    }
    float acc = 0.f;
    for (int d0 = 0; d0 < 192; d0 += 96) {
        __syncthreads();
        for (int i = tid; i < 96*38; i += 320) {
            sWf[i] = g_Wf[d0*38 + i];
            sWb[i] = g_Wb[d0*38 + i];
        }
        __syncthreads();
        if (j < 38) {
#pragma unroll 8
            for (int dd = 0; dd < 96; dd++) {
                acc += sXf[li*192 + d0 + dd]*sWf[dd*38 + j]
                     + sXb[li*192 + d0 + dd]*sWb[dd*38 + j];
            }
        }
    }
    if (j < 38) {
        int lg = blockIdx.x*8 + li;
        int b = lg / LL, l = lg % LL;
        int jm = (j < 6) ? j : j + 2;
        g_xdbl[(size_t)(b*LL + l)*40 + jm] = acc;
    }
}

// ---------------- K3b: delta = softplus(dt·W_delta + b_delta) ----------------
__global__ void k3b_delta(const float* __restrict__ W_delta, const float* __restrict__ b_delta) {
    int g = blockIdx.x*256 + threadIdx.x;          // < BB*LL*768
    int e = g % 768;
    int rem = g / 768;
    int l = rem % LL;
    int b = rem / LL;
    const float* row = &g_xdbl[(size_t)(b*LL + l)*40];
    float acc = b_delta[e];
#pragma unroll
    for (int r = 0; r < 6; r++) acc += row[r]*W_delta[r*768 + e];
    float sp = (acc > 20.f) ? acc : log1pf(__expf(acc));
    g_delta[(size_t)(b*LL + l)*768 + e] = sp;
}

// ---------------- K4a: scan pass A (chunk-local, h0 = 0) ----------------
__global__ void k4a_scanA() {
    __shared__ float sB[CLEN*NST];
    int tid = threadIdx.x;
    int d4 = blockIdx.x*128 + tid;
    int c  = blockIdx.y;
    int b  = blockIdx.z;
    int l0 = c*CLEN;
    for (int i = tid; i < CLEN*NST; i += 128)
        sB[i] = g_xdbl[(size_t)(b*LL + l0 + (i>>4))*40 + 8 + (i&15)];
    __syncthreads();

    float An[NST];
#pragma unroll
    for (int n = 0; n < NST; n++) An[n] = g_A[d4*NST + n];
    bool fwd = d4 < 384;
    int du = d4 % 192;

    float h[NST], p[NST];
#pragma unroll
    for (int n = 0; n < NST; n++) { h[n] = 0.f; p[n] = 1.f; }

    for (int i = 0; i < CLEN; i++) {
        int l = l0 + i;
        float dl = g_delta[(size_t)(b*LL + l)*768 + d4];
        int lu = fwd ? l : (LL-1-l);
        float u = g_xc[(size_t)(b*LL + lu)*192 + du];
        float s = dl*u;
        const float4* b4 = (const float4*)(sB + i*16);
        float4 b0 = b4[0], b1 = b4[1], b2 = b4[2], b3 = b4[3];
        float bn[NST] = {b0.x,b0.y,b0.z,b0.w,b1.x,b1.y,b1.z,b1.w,
                         b2.x,b2.y,b2.z,b2.w,b3.x,b3.y,b3.z,b3.w};
#pragma unroll
        for (int n = 0; n < NST; n++) {
            float a = __expf(dl*An[n]);
            h[n] = a*h[n] + s*bn[n];
            p[n] *= a;
        }
    }
    size_t idx0 = ((size_t)(b*NCH + c)*768 + d4)*NST;
    float4* H4 = (float4*)(g_chH + idx0);
    float4* P4 = (float4*)(g_chP + idx0);
#pragma unroll
    for (int k = 0; k < 4; k++) {
        H4[k] = make_float4(h[4*k],h[4*k+1],h[4*k+2],h[4*k+3]);
        P4[k] = make_float4(p[4*k],p[4*k+1],p[4*k+2],p[4*k+3]);
    }
}

// ---------------- K4b: prefix over chunks (writes h0 into g_chH) ----------------
__global__ void k4b_prefix() {
    int g = blockIdx.x*256 + threadIdx.x;          // < BB*768*16
    int n  = g & 15;
    int d4 = (g >> 4) % 768;
    int b  = g / (16*768);
    float h = 0.f;
    for (int c = 0; c < NCH; c++) {
        size_t idx = ((size_t)(b*NCH + c)*768 + d4)*NST + n;
        float hc = g_chH[idx];
        float pp = g_chP[idx];
        g_chH[idx] = h;                 // becomes h0 for this chunk
        h = fmaf(pp, h, hc);
    }
}

// ---------------- K4c: scan pass C (replay with h0, emit y) ----------------
__global__ void k4c_scanC(const float* __restrict__ Dp) {
    __shared__ float sB[CLEN*NST];
    __shared__ float sC[CLEN*NST];
    int tid = threadIdx.x;
    int d4 = blockIdx.x*128 + tid;
    int c  = blockIdx.y;
    int b  = blockIdx.z;
    int l0 = c*CLEN;
    for (int i = tid; i < CLEN*NST; i += 128) {
        size_t base = (size_t)(b*LL + l0 + (i>>4))*40;
        sB[i] = g_xdbl[base + 8  + (i&15)];
        sC[i] = g_xdbl[base + 24 + (i&15)];
    }
    __syncthreads();

    float An[NST];
#pragma unroll
    for (int n = 0; n < NST; n++) An[n] = g_A[d4*NST + n];
    bool fwd = d4 < 384;
    int du = d4 % 192;
    float dp = Dp[d4];

    size_t idx0 = ((size_t)(b*NCH + c)*768 + d4)*NST;
    const float4* H4 = (const float4*)(g_chH + idx0);
    float h[NST];
#pragma unroll
    for (int k = 0; k < 4; k++) {
        float4 hv = H4[k];
        h[4*k] = hv.x; h[4*k+1] = hv.y; h[4*k+2] = hv.z; h[4*k+3] = hv.w;
    }

    for (int i = 0; i < CLEN; i++) {
        int l = l0 + i;
        float dl = g_delta[(size_t)(b*LL + l)*768 + d4];
        int lu = fwd ? l : (LL-1-l);
        float u = g_xc[(size_t)(b*LL + lu)*192 + du];
        float s = dl*u;
        const float4* b4 = (const float4*)(sB + i*16);
        const float4* c4 = (const float4*)(sC + i*16);
        float4 b0=b4[0],b1=b4[1],b2=b4[2],b3=b4[3];
        float4 c0=c4[0],c1=c4[1],c2=c4[2],c3=c4[3];
        float bn[NST] = {b0.x,b0.y,b0.z,b0.w,b1.x,b1.y,b1.z,b1.w,
                         b2.x,b2.y,b2.z,b2.w,b3.x,b3.y,b3.z,b3.w};
        float cn[NST] = {c0.x,c0.y,c0.z,c0.w,c1.x,c1.y,c1.z,c1.w,
                         c2.x,c2.y,c2.z,c2.w,c3.x,c3.y,c3.z,c3.w};
        float y = dp*u;
#pragma unroll
        for (int n = 0; n < NST; n++) {
            float a = __expf(dl*An[n]);
            h[n] = a*h[n] + s*bn[n];
            y += h[n]*cn[n];
        }
        g_y[(size_t)(b*LL + l)*768 + d4] = y;
    }
}

// ---------------- K5: combine 4 dirs + LayerNorm + gate + out GEMM ----------------
// block: 192 threads, 16 pixels per block, W_out staged in dynamic smem.
#define K5_SMEM_FLOATS (192*96 + 192 + 192 + 16)
__global__ void k5_out(const float* __restrict__ ln_g, const float* __restrict__ ln_b,
                       const float* __restrict__ W_out, float* __restrict__ out) {
    extern __shared__ float sm[];
    float* sW    = sm;                 // 192*96
    float* sg    = sm + 192*96;        // 192
    float* sPart = sg + 192;           // 192
    float* sRed  = sPart + 192;        // 16

    int tid = threadIdx.x;
    int b  = blockIdx.y;
    int p0 = blockIdx.x*16;

    for (int i = tid; i < 192*96; i += 192) sW[i] = W_out[i];
    float lg = ln_g[tid], lb = ln_b[tid];
    int c = tid % 96, halfq = tid / 96;
    float outv[16];
    __syncthreads();

    for (int pi = 0; pi < 16; pi++) {
        int p = p0 + pi, pf = LL - 1 - p;
        const float* yr  = g_y + (size_t)(b*LL + p)*768;
        const float* yrf = g_y + (size_t)(b*LL + pf)*768;
        float v = yr[tid] + yr[192 + tid] + yrf[384 + tid] + yrf[576 + tid];

        float s1 = v, s2 = v*v;
#pragma unroll
        for (int off = 16; off >= 1; off >>= 1) {
            s1 += __shfl_xor_sync(0xffffffffu, s1, off);
            s2 += __shfl_xor_sync(0xffffffffu, s2, off);
        }
        int wid = tid >> 5, lane = tid & 31;
        if (lane == 0) { sRed[wid] = s1; sRed[8 + wid] = s2; }
        __syncthreads();
        if (tid == 0) {
            float a = 0.f, q = 0.f;
            for (int w = 0; w < 6; w++) { a += sRed[w]; q += sRed[8 + w]; }
            float mu = a * (1.f/192.f);
            float var = q * (1.f/192.f) - mu*mu;
            sRed[14] = mu;
            sRed[15] = rsqrtf(var + 1e-5f);
        }
        __syncthreads();
        float mu = sRed[14], rstd = sRed[15];
        float yn = (v - mu)*rstd*lg + lb;
        float zv = g_xz[(size_t)(b*LL + p)*384 + 192 + tid];
        float gval = yn * zv / (1.f + __expf(-zv));
        sg[tid] = gval;
        __syncthreads();

        float part = 0.f;
#pragma unroll 8
        for (int k = 0; k < 96; k++) {
            int d = halfq*96 + k;
            part += sg[d]*sW[d*96 + c];
        }
        sPart[tid] = part;
        __syncthreads();
        if (tid < 96) outv[pi] = sPart[tid] + sPart[96 + tid];
        __syncthreads();
    }
    if (tid < 96) {
        for (int pi = 0; pi < 16; pi++)
            out[(size_t)(b*96 + tid)*LL + p0 + pi] = outv[pi];
    }
}

// ---------------- launch ----------------
extern "C" void kernel_launch(void* const* d_in, const int* in_sizes, int n_in,
                              void* d_out, int out_size) {
    const float* x       = (const float*)d_in[0];
    const float* W_in    = (const float*)d_in[1];
    const float* b_in    = (const float*)d_in[2];
    const float* w_dw    = (const float*)d_in[3];
    const float* b_dw    = (const float*)d_in[4];
    const float* A_log   = (const float*)d_in[5];
    const float* Dp      = (const float*)d_in[6];
    const float* W_x     = (const float*)d_in[7];
    const float* W_delta = (const float*)d_in[8];
    const float* b_delta = (const float*)d_in[9];
    const float* ln_g    = (const float*)d_in[10];
    const float* ln_b    = (const float*)d_in[11];
    const float* W_out   = (const float*)d_in[12];
    float* out = (float*)d_out;

    cudaFuncSetAttribute(k5_out, cudaFuncAttributeMaxDynamicSharedMemorySize,
                         K5_SMEM_FLOATS * (int)sizeof(float));

    k_prep<<<48, 256>>>(A_log, W_x);
    k1_inproj<<<dim3(LL/64, BB), 512>>>(x, W_in, b_in);
    k2_conv<<<(BB*LL*192)/256, 256>>>(w_dw, b_dw);
    k3a_xdbl<<<(BB*LL)/8, 320>>>();
    k3b_delta<<<(BB*LL*768)/256, 256>>>(W_delta, b_delta);
    k4a_scanA<<<dim3(6, NCH, BB), 128>>>();
    k4b_prefix<<<(BB*768*16)/256, 256>>>();
    k4c_scanC<<<dim3(6, NCH, BB), 128>>>(Dp);
    k5_out<<<dim3(LL/16, BB), 192, K5_SMEM_FLOATS*(int)sizeof(float)>>>(ln_g, ln_b, W_out, out);
}

// round 2
// speedup vs baseline: 1.1880x; 1.1880x over previous
#include <cuda_runtime.h>
#include <cuda_bf16.h>
#include <math.h>

#define BB   2
#define LL   9216
#define HH   96
#define WIMG 96
#define D2C  192
#define D4C  768
#define NST  16
#define NCH  96   // number of scan chunks
#define CLEN 96   // chunk length  (NCH*CLEN == LL)

// ---------------- scratch (device globals; no allocation) ----------------
__device__ float g_xz   [BB*LL*384];       // (b,l,384): xx | z
__device__ float g_xc   [BB*LL*D2C];       // conv+silu output, (b,l,192)
__device__ float g_xdbl [BB*LL*40];        // dt[0:6) pad[6:8) B[8:24) C[24:40)
__device__ float g_delta[BB*LL*D4C];       // softplus deltas
__device__ float g_y    [BB*LL*D4C];       // scan outputs
__device__ float g_chH  [BB*NCH*D4C*NST];  // chunk local end-state -> then h0
__device__ float g_chP  [BB*NCH*D4C*NST];  // chunk a-products
__device__ float g_A    [D4C*NST];         // -exp(A_log)
__device__ float g_Wf   [D2C*40];          // folded forward W_x (padded to 40)
__device__ float g_Wb   [D2C*40];          // folded backward W_x (padded to 40)

// ---------------- prep: A table + folded W_x ----------------
__global__ void k_prep(const float* __restrict__ A_log, const float* __restrict__ W_x) {
    int i = blockIdx.x*256 + threadIdx.x;
    if (i < D4C*NST) g_A[i] = -expf(A_log[i]);
    if (i < D2C*40) {
        int d = i/40, j = i%40;
        float vf = 0.f, vb = 0.f;
        if (j < 38) {
            vf = W_x[d*38+j]       + W_x[(d+192)*38+j];
            vb = W_x[(d+384)*38+j] + W_x[(d+576)*38+j];
        }
        g_Wf[i] = vf;
        g_Wb[i] = vb;
    }
}

// ---------------- K1: in-projection GEMM (96 -> 384 per pixel) ----------------
__global__ void k1_inproj(const float* __restrict__ x,
                          const float* __restrict__ W_in,
                          const float* __restrict__ b_in) {
    __shared__ float sX[24*64];
    __shared__ float sW[24*384];
    int tid = threadIdx.x;
    int b  = blockIdx.y;
    int l0 = blockIdx.x*64;
    int eg = tid & 31;
    int jq = tid >> 5;
    float4 acc[12];
#pragma unroll
    for (int ei = 0; ei < 12; ei++) acc[ei] = make_float4(0.f,0.f,0.f,0.f);

    for (int c0 = 0; c0 < 96; c0 += 24) {
        __syncthreads();
        for (int i = tid; i < 24*64; i += 512) {
            int c = i >> 6, j = i & 63;
            sX[i] = x[(b*96 + c0 + c)*LL + l0 + j];
        }
        for (int i = tid; i < 24*384; i += 512)
            sW[i] = W_in[c0*384 + i];
        __syncthreads();
#pragma unroll
        for (int cc = 0; cc < 24; cc++) {
            float4 xv = *(const float4*)(sX + cc*64 + jq*4);
#pragma unroll
            for (int ei = 0; ei < 12; ei++) {
                float w = sW[cc*384 + ei*32 + eg];
                acc[ei].x += xv.x*w; acc[ei].y += xv.y*w;
                acc[ei].z += xv.z*w; acc[ei].w += xv.w*w;
            }
        }
    }
    int lbase = l0 + jq*4;
#pragma unroll
    for (int ei = 0; ei < 12; ei++) {
        int e = ei*32 + eg;
        float bb = b_in[e];
        g_xz[(size_t)(b*LL + lbase+0)*384 + e] = acc[ei].x + bb;
        g_xz[(size_t)(b*LL + lbase+1)*384 + e] = acc[ei].y + bb;
        g_xz[(size_t)(b*LL + lbase+2)*384 + e] = acc[ei].z + bb;
        g_xz[(size_t)(b*LL + lbase+3)*384 + e] = acc[ei].w + bb;
    }
}

// ---------------- K2: depthwise 3x3 conv + bias + SiLU ----------------
__global__ void k2_conv(const float* __restrict__ w_dw, const float* __restrict__ b_dw) {
    int g = blockIdx.x*256 + threadIdx.x;
    int d = g % 192;
    int rem = g / 192;
    int l = rem % LL;
    int b = rem / LL;
    int h = l / WIMG, w = l % WIMG;
    float acc = b_dw[d];
#pragma unroll
    for (int kh = -1; kh <= 1; kh++) {
        int hh = h + kh;
        if (hh < 0 || hh >= HH) continue;
#pragma unroll
        for (int kw = -1; kw <= 1; kw++) {
            int ww = w + kw;
            if (ww < 0 || ww >= WIMG) continue;
            acc += g_xz[(size_t)(b*LL + hh*WIMG + ww)*384 + d]
                 * w_dw[d*9 + (kh+1)*3 + (kw+1)];
        }
    }
    float val = acc / (1.f + __expf(-acc));
    g_xc[(size_t)(b*LL + l)*192 + d] = val;
}

// ---------------- K3a: x_dbl = flat·Wf + flip·Wb  (register tiled) ----------------
// grid (72, BB), block 256, dynamic smem. Tile: 128 pixels x 40 outputs.
// Thread (pg,jg): 4 pixels x 5 outputs.
#define K3_PITCH 132
#define K3_SMEM_FLOATS (96*K3_PITCH*2 + 96*40*2)
__global__ void k3a_xdbl() {
    extern __shared__ float sm3[];
    float* sXf = sm3;
    float* sXb = sXf + 96*K3_PITCH;
    float* sWf = sXb + 96*K3_PITCH;
    float* sWb = sWf + 96*40;
    int tid = threadIdx.x;
    int b  = blockIdx.y;
    int l0 = blockIdx.x*128;
    int pg = tid >> 3;      // 0..31
    int jg = tid & 7;       // 0..7
    float acc[4][5];
#pragma unroll
    for (int p = 0; p < 4; p++)
#pragma unroll
        for (int q = 0; q < 5; q++) acc[p][q] = 0.f;

    for (int d0 = 0; d0 < 192; d0 += 96) {
        __syncthreads();
        for (int i = tid; i < 128*96; i += 256) {
            int pix = i / 96, dd = i % 96;
            int l = l0 + pix;
            sXf[dd*K3_PITCH + pix] = g_xc[(size_t)(b*LL + l)*192 + d0 + dd];
            sXb[dd*K3_PITCH + pix] = g_xc[(size_t)(b*LL + (LL-1-l))*192 + d0 + dd];
        }
        for (int i = tid; i < 96*40; i += 256) {
            sWf[i] = g_Wf[d0*40 + i];
            sWb[i] = g_Wb[d0*40 + i];
        }
        __syncthreads();
#pragma unroll 4
        for (int dd = 0; dd < 96; dd++) {
            float4 xf4 = *(const float4*)(sXf + dd*K3_PITCH + pg*4);
            float4 xb4 = *(const float4*)(sXb + dd*K3_PITCH + pg*4);
            float xf[4] = {xf4.x, xf4.y, xf4.z, xf4.w};
            float xb[4] = {xb4.x, xb4.y, xb4.z, xb4.w};
            float wf[5], wb[5];
#pragma unroll
            for (int q = 0; q < 5; q++) {
                wf[q] = sWf[dd*40 + jg*5 + q];
                wb[q] = sWb[dd*40 + jg*5 + q];
            }
#pragma unroll
            for (int p = 0; p < 4; p++)
#pragma unroll
                for (int q = 0; q < 5; q++)
                    acc[p][q] += xf[p]*wf[q] + xb[p]*wb[q];
        }
    }
#pragma unroll
    for (int q = 0; q < 5; q++) {
        int j = jg*5 + q;
        if (j < 38) {
            int jm = (j < 6) ? j : j + 2;
#pragma unroll
            for (int p = 0; p < 4; p++) {
                int l = l0 + pg*4 + p;
                g_xdbl[(size_t)(b*LL + l)*40 + jm] = acc[p][q];
            }
        }
    }
}

// ---------------- K3b: delta = softplus(dt·W_delta + b_delta) ----------------
__global__ void k3b_delta(const float* __restrict__ W_delta, const float* __restrict__ b_delta) {
    int g = blockIdx.x*256 + threadIdx.x;
    int e = g % 768;
    int rem = g / 768;
    int l = rem % LL;
    int b = rem / LL;
    const float* row = &g_xdbl[(size_t)(b*LL + l)*40];
    float acc = b_delta[e];
#pragma unroll
    for (int r = 0; r < 6; r++) acc += row[r]*W_delta[r*768 + e];
    float sp = (acc > 20.f) ? acc : log1pf(__expf(acc));
    g_delta[(size_t)(b*LL + l)*768 + e] = sp;
}

// helper: check A_n == A_0*(n+1) (true for this model: A_n = -(n+1))
__device__ __forceinline__ bool a_structured(const float* An) {
    bool ok = true;
#pragma unroll
    for (int n = 1; n < NST; n++)
        ok = ok && (fabsf(An[n] - An[0]*(float)(n+1)) <= 1e-5f*(float)(n+1));
    return ok;
}

// ---------------- K4a: scan pass A (chunk-local, h0 = 0) ----------------
__global__ void k4a_scanA() {
    __shared__ float sB[CLEN*NST];
    int tid = threadIdx.x;
    int d4 = blockIdx.x*128 + tid;
    int c  = blockIdx.y;
    int b  = blockIdx.z;
    int l0 = c*CLEN;
    for (int i = tid; i < CLEN*NST; i += 128)
        sB[i] = g_xdbl[(size_t)(b*LL + l0 + (i>>4))*40 + 8 + (i&15)];
    __syncthreads();

    float An[NST];
#pragma unroll
    for (int n = 0; n < NST; n++) An[n] = g_A[d4*NST + n];
    bool sA = a_structured(An);
    bool fwd = d4 < 384;
    int du = d4 % 192;

    float h[NST];
#pragma unroll
    for (int n = 0; n < NST; n++) h[n] = 0.f;
    float S = 0.f;

    if (sA) {
        for (int i = 0; i < CLEN; i++) {
            int l = l0 + i;
            float dl = g_delta[(size_t)(b*LL + l)*768 + d4];
            int lu = fwd ? l : (LL-1-l);
            float u = g_xc[(size_t)(b*LL + lu)*192 + du];
            float s = dl*u;
            S += dl;
            float e1 = __expf(dl*An[0]);
            float a = e1;
            const float* bn = sB + i*16;
#pragma unroll
            for (int n = 0; n < NST; n++) {
                h[n] = fmaf(a, h[n], s*bn[n]);
                a *= e1;
            }
        }
    } else {
        for (int i = 0; i < CLEN; i++) {
            int l = l0 + i;
            float dl = g_delta[(size_t)(b*LL + l)*768 + d4];
            int lu = fwd ? l : (LL-1-l);
            float u = g_xc[(size_t)(b*LL + lu)*192 + du];
            float s = dl*u;
            S += dl;
            const float* bn = sB + i*16;
#pragma unroll
            for (int n = 0; n < NST; n++) {
                float a = __expf(dl*An[n]);
                h[n] = fmaf(a, h[n], s*bn[n]);
            }
        }
    }

    // chunk a-product: p_n = exp(A_n * sum(delta))  (exact, any A)
    float p[NST];
    if (sA) {
        float E = __expf(S*An[0]);
        float a = E;
#pragma unroll
        for (int n = 0; n < NST; n++) { p[n] = a; a *= E; }
    } else {
#pragma unroll
        for (int n = 0; n < NST; n++) p[n] = __expf(S*An[n]);
    }

    size_t idx0 = ((size_t)(b*NCH + c)*768 + d4)*NST;
    float4* H4 = (float4*)(g_chH + idx0);
    float4* P4 = (float4*)(g_chP + idx0);
#pragma unroll
    for (int k = 0; k < 4; k++) {
        H4[k] = make_float4(h[4*k],h[4*k+1],h[4*k+2],h[4*k+3]);
        P4[k] = make_float4(p[4*k],p[4*k+1],p[4*k+2],p[4*k+3]);
    }
}

// ---------------- K4b: prefix over chunks (writes h0 into g_chH) ----------------
__global__ void k4b_prefix() {
    int g = blockIdx.x*256 + threadIdx.x;
    int n  = g & 15;
    int d4 = (g >> 4) % 768;
    int b  = g / (16*768);
    float h = 0.f;
    for (int c = 0; c < NCH; c++) {
        size_t idx = ((size_t)(b*NCH + c)*768 + d4)*NST + n;
        float hc = g_chH[idx];
        float pp = g_chP[idx];
        g_chH[idx] = h;
        h = fmaf(pp, h, hc);
    }
}

// ---------------- K4c: scan pass C (replay with h0, emit y) ----------------
__global__ void k4c_scanC(const float* __restrict__ Dp) {
    __shared__ float sB[CLEN*NST];
    __shared__ float sC[CLEN*NST];
    int tid = threadIdx.x;
    int d4 = blockIdx.x*128 + tid;
    int c  = blockIdx.y;
    int b  = blockIdx.z;
    int l0 = c*CLEN;
    for (int i = tid; i < CLEN*NST; i += 128) {
        size_t base = (size_t)(b*LL + l0 + (i>>4))*40;
        sB[i] = g_xdbl[base + 8  + (i&15)];
        sC[i] = g_xdbl[base + 24 + (i&15)];
    }
    __syncthreads();

    float An[NST];
#pragma unroll
    for (int n = 0; n < NST; n++) An[n] = g_A[d4*NST + n];
    bool sA = a_structured(An);
    bool fwd = d4 < 384;
    int du = d4 % 192;
    float dp = Dp[d4];

    size_t idx0 = ((size_t)(b*NCH + c)*768 + d4)*NST;
    const float4* H4 = (const float4*)(g_chH + idx0);
    float h[NST];
#pragma unroll
    for (int k = 0; k < 4; k++) {
        float4 hv = H4[k];
        h[4*k] = hv.x; h[4*k+1] = hv.y; h[4*k+2] = hv.z; h[4*k+3] = hv.w;
    }

    if (sA) {
        for (int i = 0; i < CLEN; i++) {
            int l = l0 + i;
            float dl = g_delta[(size_t)(b*LL + l)*768 + d4];
            int lu = fwd ? l : (LL-1-l);
            float u = g_xc[(size_t)(b*LL + lu)*192 + du];
            float s = dl*u;
            float e1 = __expf(dl*An[0]);
            float a = e1;
            const float* bn = sB + i*16;
            const float* cn = sC + i*16;
            float y = dp*u;
#pragma unroll
            for (int n = 0; n < NST; n++) {
                h[n] = fmaf(a, h[n], s*bn[n]);
                y = fmaf(h[n], cn[n], y);
                a *= e1;
            }
            g_y[(size_t)(b*LL + l)*768 + d4] = y;
        }
    } else {
        for (int i = 0; i < CLEN; i++) {
            int l = l0 + i;
            float dl = g_delta[(size_t)(b*LL + l)*768 + d4];
            int lu = fwd ? l : (LL-1-l);
            float u = g_xc[(size_t)(b*LL + lu)*192 + du];
            float s = dl*u;
            const float* bn = sB + i*16;
            const float* cn = sC + i*16;
            float y = dp*u;
#pragma unroll
            for (int n = 0; n < NST; n++) {
                float a = __expf(dl*An[n]);
                h[n] = fmaf(a, h[n], s*bn[n]);
                y = fmaf(h[n], cn[n], y);
            }
            g_y[(size_t)(b*LL + l)*768 + d4] = y;
        }
    }
}

// ---------------- K5: combine 4 dirs + LayerNorm + gate + out GEMM ----------------
#define K5_SMEM_FLOATS (192*96 + 192 + 192 + 16)
__global__ void k5_out(const float* __restrict__ ln_g, const float* __restrict__ ln_b,
                       const float* __restrict__ W_out, float* __restrict__ out) {
    extern __shared__ float sm[];
    float* sW    = sm;
    float* sg    = sm + 192*96;
    float* sPart = sg + 192;
    float* sRed  = sPart + 192;

    int tid = threadIdx.x;
    int b  = blockIdx.y;
    int p0 = blockIdx.x*16;

    for (int i = tid; i < 192*96; i += 192) sW[i] = W_out[i];
    float lg = ln_g[tid], lb = ln_b[tid];
    int c = tid % 96, halfq = tid / 96;
    float outv[16];
    __syncthreads();

    for (int pi = 0; pi < 16; pi++) {
        int p = p0 + pi, pf = LL - 1 - p;
        const float* yr  = g_y + (size_t)(b*LL + p)*768;
        const float* yrf = g_y + (size_t)(b*LL + pf)*768;
        float v = yr[tid] + yr[192 + tid] + yrf[384 + tid] + yrf[576 + tid];

        float s1 = v, s2 = v*v;
#pragma unroll
        for (int off = 16; off >= 1; off >>= 1) {
            s1 += __shfl_xor_sync(0xffffffffu, s1, off);
            s2 += __shfl_xor_sync(0xffffffffu, s2, off);
        }
        int wid = tid >> 5, lane = tid & 31;
        if (lane == 0) { sRed[wid] = s1; sRed[8 + wid] = s2; }
        __syncthreads();
        if (tid == 0) {
            float a = 0.f, q = 0.f;
            for (int w = 0; w < 6; w++) { a += sRed[w]; q += sRed[8 + w]; }
            float mu = a * (1.f/192.f);
            float var = q * (1.f/192.f) - mu*mu;
            sRed[14] = mu;
            sRed[15] = rsqrtf(var + 1e-5f);
        }
        __syncthreads();
        float mu = sRed[14], rstd = sRed[15];
        float yn = (v - mu)*rstd*lg + lb;
        float zv = g_xz[(size_t)(b*LL + p)*384 + 192 + tid];
        float gval = yn * zv / (1.f + __expf(-zv));
        sg[tid] = gval;
        __syncthreads();

        float part = 0.f;
#pragma unroll 8
        for (int k = 0; k < 96; k++) {
            int d = halfq*96 + k;
            part += sg[d]*sW[d*96 + c];
        }
        sPart[tid] = part;
        __syncthreads();
        if (tid < 96) outv[pi] = sPart[tid] + sPart[96 + tid];
        __syncthreads();
    }
    if (tid < 96) {
        for (int pi = 0; pi < 16; pi++)
            out[(size_t)(b*96 + tid)*LL + p0 + pi] = outv[pi];
    }
}

// ---------------- launch ----------------
extern "C" void kernel_launch(void* const* d_in, const int* in_sizes, int n_in,
                              void* d_out, int out_size) {
    const float* x       = (const float*)d_in[0];
    const float* W_in    = (const float*)d_in[1];
    const float* b_in    = (const float*)d_in[2];
    const float* w_dw    = (const float*)d_in[3];
    const float* b_dw    = (const float*)d_in[4];
    const float* A_log   = (const float*)d_in[5];
    const float* Dp      = (const float*)d_in[6];
    const float* W_x     = (const float*)d_in[7];
    const float* W_delta = (const float*)d_in[8];
    const float* b_delta = (const float*)d_in[9];
    const float* ln_g    = (const float*)d_in[10];
    const float* ln_b    = (const float*)d_in[11];
    const float* W_out   = (const float*)d_in[12];
    float* out = (float*)d_out;

    cudaFuncSetAttribute(k5_out, cudaFuncAttributeMaxDynamicSharedMemorySize,
                         K5_SMEM_FLOATS * (int)sizeof(float));
    cudaFuncSetAttribute(k3a_xdbl, cudaFuncAttributeMaxDynamicSharedMemorySize,
                         K3_SMEM_FLOATS * (int)sizeof(float));

    k_prep<<<48, 256>>>(A_log, W_x);
    k1_inproj<<<dim3(LL/64, BB), 512>>>(x, W_in, b_in);
    k2_conv<<<(BB*LL*192)/256, 256>>>(w_dw, b_dw);
    k3a_xdbl<<<dim3(72, BB), 256, K3_SMEM_FLOATS*(int)sizeof(float)>>>();
    k3b_delta<<<(BB*LL*768)/256, 256>>>(W_delta, b_delta);
    k4a_scanA<<<dim3(6, NCH, BB), 128>>>();
    k4b_prefix<<<(BB*768*16)/256, 256>>>();
    k4c_scanC<<<dim3(6, NCH, BB), 128>>>(Dp);
    k5_out<<<dim3(LL/16, BB), 192, K5_SMEM_FLOATS*(int)sizeof(float)>>>(ln_g, ln_b, W_out, out);
}

// round 3
// speedup vs baseline: 1.6703x; 1.4059x over previous
#include <cuda_runtime.h>
#include <cuda_bf16.h>
#include <math.h>

#define BB   2
#define LL   9216
#define HH   96
#define WIMG 96
#define D2C  192
#define D4C  768
#define NST  16
#define NCH  96
#define CLEN 96

// ---------------- scratch (device globals; no allocation) ----------------
__device__ float g_xz   [BB*LL*384];       // (b,l,384): xx | z
__device__ float g_xc   [BB*LL*D2C];       // conv+silu output, (b,l,192)
__device__ float g_xdp  [2][BB*LL*40];     // k3a partials (per d-half)
__device__ float g_xdbl [BB*LL*40];        // dt[0:6) pad[6:8) B[8:24) C[24:40)
__device__ float g_y    [BB*LL*D4C];       // scan outputs
__device__ float g_gT   [BB*D2C*LL];       // gated values, d-major transposed
__device__ float g_chH  [BB*NCH*D4C*NST];  // chunk local end-state -> then h0
__device__ float g_chP  [BB*NCH*D4C*NST];  // chunk a-products
__device__ float g_A    [D4C*NST];         // -exp(A_log)
__device__ float g_Wf   [D2C*40];          // folded forward W_x (padded)
__device__ float g_Wb   [D2C*40];          // folded backward W_x (padded)

// ---------------- prep ----------------
__global__ void k_prep(const float* __restrict__ A_log, const float* __restrict__ W_x) {
    int i = blockIdx.x*256 + threadIdx.x;
    if (i < D4C*NST) g_A[i] = -expf(A_log[i]);
    if (i < D2C*40) {
        int d = i/40, j = i%40;
        float vf = 0.f, vb = 0.f;
        if (j < 38) {
            vf = W_x[d*38+j]       + W_x[(d+192)*38+j];
            vb = W_x[(d+384)*38+j] + W_x[(d+576)*38+j];
        }
        g_Wf[i] = vf;
        g_Wb[i] = vb;
    }
}

// ---------------- K1: in-projection GEMM (96 -> 384 per pixel) ----------------
__global__ void k1_inproj(const float* __restrict__ x,
                          const float* __restrict__ W_in,
                          const float* __restrict__ b_in) {
    __shared__ float sX[24*64];
    __shared__ float sW[24*384];
    int tid = threadIdx.x;
    int b  = blockIdx.y;
    int l0 = blockIdx.x*64;
    int eg = tid & 31;
    int jq = tid >> 5;
    float4 acc[12];
#pragma unroll
    for (int ei = 0; ei < 12; ei++) acc[ei] = make_float4(0.f,0.f,0.f,0.f);

    for (int c0 = 0; c0 < 96; c0 += 24) {
        __syncthreads();
        for (int i = tid; i < 24*64; i += 512) {
            int c = i >> 6, j = i & 63;
            sX[i] = x[(b*96 + c0 + c)*LL + l0 + j];
        }
        for (int i = tid; i < 24*384; i += 512)
            sW[i] = W_in[c0*384 + i];
        __syncthreads();
#pragma unroll
        for (int cc = 0; cc < 24; cc++) {
            float4 xv = *(const float4*)(sX + cc*64 + jq*4);
#pragma unroll
            for (int ei = 0; ei < 12; ei++) {
                float w = sW[cc*384 + ei*32 + eg];
                acc[ei].x += xv.x*w; acc[ei].y += xv.y*w;
                acc[ei].z += xv.z*w; acc[ei].w += xv.w*w;
            }
        }
    }
    int lbase = l0 + jq*4;
#pragma unroll
    for (int ei = 0; ei < 12; ei++) {
        int e = ei*32 + eg;
        float bb = b_in[e];
        g_xz[(size_t)(b*LL + lbase+0)*384 + e] = acc[ei].x + bb;
        g_xz[(size_t)(b*LL + lbase+1)*384 + e] = acc[ei].y + bb;
        g_xz[(size_t)(b*LL + lbase+2)*384 + e] = acc[ei].z + bb;
        g_xz[(size_t)(b*LL + lbase+3)*384 + e] = acc[ei].w + bb;
    }
}

// ---------------- K2: depthwise 3x3 conv + bias + SiLU ----------------
__global__ void k2_conv(const float* __restrict__ w_dw, const float* __restrict__ b_dw) {
    int g = blockIdx.x*256 + threadIdx.x;
    int d = g % 192;
    int rem = g / 192;
    int l = rem % LL;
    int b = rem / LL;
    int h = l / WIMG, w = l % WIMG;
    float acc = b_dw[d];
#pragma unroll
    for (int kh = -1; kh <= 1; kh++) {
        int hh = h + kh;
        if (hh < 0 || hh >= HH) continue;
#pragma unroll
        for (int kw = -1; kw <= 1; kw++) {
            int ww = w + kw;
            if (ww < 0 || ww >= WIMG) continue;
            acc += g_xz[(size_t)(b*LL + hh*WIMG + ww)*384 + d]
                 * w_dw[d*9 + (kh+1)*3 + (kw+1)];
        }
    }
    float val = acc / (1.f + __expf(-acc));
    g_xc[(size_t)(b*LL + l)*192 + d] = val;
}

// ---------------- K3a: x_dbl partials, d-half split for occupancy ----------------
// grid (72, 2, BB), 256 threads. 128 pixels x 40 outputs, 96-d reduction per block.
__global__ void k3a_xdbl() {
    __shared__ float sXf[32*132];
    __shared__ float sXb[32*132];
    __shared__ float sWf[96*40];
    __shared__ float sWb[96*40];
    int tid = threadIdx.x;
    int b  = blockIdx.z;
    int dh = blockIdx.y;
    int l0 = blockIdx.x*128;
    int d0 = dh*96;
    int pg = tid >> 3;      // 0..31 (4 pixels each)
    int jg = tid & 7;       // 0..7  (5 outputs each)

    for (int i = tid; i < 96*40; i += 256) {
        sWf[i] = g_Wf[d0*40 + i];
        sWb[i] = g_Wb[d0*40 + i];
    }
    float acc[4][5];
#pragma unroll
    for (int p = 0; p < 4; p++)
#pragma unroll
        for (int q = 0; q < 5; q++) acc[p][q] = 0.f;

    for (int ch = 0; ch < 3; ch++) {
        __syncthreads();
        int db = d0 + ch*32;
        for (int i = tid; i < 128*32; i += 256) {
            int pix = i >> 5, dd = i & 31;
            int l = l0 + pix;
            sXf[dd*132 + pix] = g_xc[(size_t)(b*LL + l)*192 + db + dd];
            sXb[dd*132 + pix] = g_xc[(size_t)(b*LL + (LL-1-l))*192 + db + dd];
        }
        __syncthreads();
#pragma unroll 4
        for (int dd = 0; dd < 32; dd++) {
            float4 xf4 = *(const float4*)(sXf + dd*132 + pg*4);
            float4 xb4 = *(const float4*)(sXb + dd*132 + pg*4);
            float xf[4] = {xf4.x, xf4.y, xf4.z, xf4.w};
            float xb[4] = {xb4.x, xb4.y, xb4.z, xb4.w};
            int wrow = (ch*32 + dd)*40 + jg*5;
            float wf[5], wb[5];
#pragma unroll
            for (int q = 0; q < 5; q++) { wf[q] = sWf[wrow+q]; wb[q] = sWb[wrow+q]; }
#pragma unroll
            for (int p = 0; p < 4; p++)
#pragma unroll
                for (int q = 0; q < 5; q++)
                    acc[p][q] += xf[p]*wf[q] + xb[p]*wb[q];
        }
    }
#pragma unroll
    for (int q = 0; q < 5; q++) {
        int j = jg*5 + q;
        if (j < 38) {
            int jm = (j < 6) ? j : j + 2;
#pragma unroll
            for (int p = 0; p < 4; p++) {
                int l = l0 + pg*4 + p;
                g_xdp[dh][(size_t)(b*LL + l)*40 + jm] = acc[p][q];
            }
        }
    }
}

// ---------------- K3s: sum the two d-half partials ----------------
__global__ void k3s_sum() {
    int i = blockIdx.x*256 + threadIdx.x;
    if (i < BB*LL*40) g_xdbl[i] = g_xdp[0][i] + g_xdp[1][i];
}

// helper: A_n == A_0*(n+1)?
__device__ __forceinline__ bool a_structured(const float* An) {
    bool ok = true;
#pragma unroll
    for (int n = 1; n < NST; n++)
        ok = ok && (fabsf(An[n] - An[0]*(float)(n+1)) <= 1e-5f*(float)(n+1));
    return ok;
}

__device__ __forceinline__ float softplusf(float a) {
    return (a > 20.f) ? a : log1pf(__expf(a));
}

// ---------------- K4a: scan pass A (chunk-local, h0 = 0, fused delta) ----------------
__global__ void k4a_scanA(const float* __restrict__ Wd, const float* __restrict__ bde) {
    __shared__ float sXD[CLEN*24];
    int tid = threadIdx.x;
    int d4 = blockIdx.x*128 + tid;
    int c  = blockIdx.y;
    int b  = blockIdx.z;
    int l0 = c*CLEN;
    for (int i = tid; i < CLEN*24; i += 128) {
        int step = i / 24, jj = i % 24;
        sXD[i] = g_xdbl[(size_t)(b*LL + l0 + step)*40 + jj];
    }
    __syncthreads();

    float wd[6];
#pragma unroll
    for (int r = 0; r < 6; r++) wd[r] = Wd[r*768 + d4];
    float bd = bde[d4];

    float An[NST];
#pragma unroll
    for (int n = 0; n < NST; n++) An[n] = g_A[d4*NST + n];
    bool sA = a_structured(An);
    bool fwd = d4 < 384;
    int du = d4 % 192;

    float h[NST];
#pragma unroll
    for (int n = 0; n < NST; n++) h[n] = 0.f;
    float S = 0.f;

    if (sA) {
        for (int i = 0; i < CLEN; i++) {
            const float* row = sXD + i*24;
            float a0 = bd;
#pragma unroll
            for (int r = 0; r < 6; r++) a0 = fmaf(row[r], wd[r], a0);
            float dl = softplusf(a0);
            S += dl;
            int l = l0 + i;
            int lu = fwd ? l : (LL-1-l);
            float u = g_xc[(size_t)(b*LL + lu)*192 + du];
            float s = dl*u;
            float e1 = __expf(dl*An[0]);
            float a = e1;
            const float* bn = row + 8;
#pragma unroll
            for (int n = 0; n < NST; n++) {
                h[n] = fmaf(a, h[n], s*bn[n]);
                a *= e1;
            }
        }
    } else {
        for (int i = 0; i < CLEN; i++) {
            const float* row = sXD + i*24;
            float a0 = bd;
#pragma unroll
            for (int r = 0; r < 6; r++) a0 = fmaf(row[r], wd[r], a0);
            float dl = softplusf(a0);
            S += dl;
            int l = l0 + i;
            int lu = fwd ? l : (LL-1-l);
            float u = g_xc[(size_t)(b*LL + lu)*192 + du];
            float s = dl*u;
            const float* bn = row + 8;
#pragma unroll
            for (int n = 0; n < NST; n++) {
                float a = __expf(dl*An[n]);
                h[n] = fmaf(a, h[n], s*bn[n]);
            }
        }
    }

    float p[NST];
    if (sA) {
        float E = __expf(S*An[0]);
        float a = E;
#pragma unroll
        for (int n = 0; n < NST; n++) { p[n] = a; a *= E; }
    } else {
#pragma unroll
        for (int n = 0; n < NST; n++) p[n] = __expf(S*An[n]);
    }

    size_t idx0 = ((size_t)(b*NCH + c)*768 + d4)*NST;
    float4* H4 = (float4*)(g_chH + idx0);
    float4* P4 = (float4*)(g_chP + idx0);
#pragma unroll
    for (int k = 0; k < 4; k++) {
        H4[k] = make_float4(h[4*k],h[4*k+1],h[4*k+2],h[4*k+3]);
        P4[k] = make_float4(p[4*k],p[4*k+1],p[4*k+2],p[4*k+3]);
    }
}

// ---------------- K4b: prefix over chunks ----------------
__global__ void k4b_prefix() {
    int g = blockIdx.x*256 + threadIdx.x;
    int n  = g & 15;
    int d4 = (g >> 4) % 768;
    int b  = g / (16*768);
    float h = 0.f;
    for (int c = 0; c < NCH; c++) {
        size_t idx = ((size_t)(b*NCH + c)*768 + d4)*NST + n;
        float hc = g_chH[idx];
        float pp = g_chP[idx];
        g_chH[idx] = h;
        h = fmaf(pp, h, hc);
    }
}

// ---------------- K4c: scan pass C (replay with h0, emit y, fused delta) ----------------
__global__ void k4c_scanC(const float* __restrict__ Dp,
                          const float* __restrict__ Wd, const float* __restrict__ bde) {
    __shared__ float sXD[CLEN*40];
    int tid = threadIdx.x;
    int d4 = blockIdx.x*128 + tid;
    int c  = blockIdx.y;
    int b  = blockIdx.z;
    int l0 = c*CLEN;
    for (int i = tid; i < CLEN*40; i += 128)
        sXD[i] = g_xdbl[(size_t)(b*LL + l0)*40 + i];
    __syncthreads();

    float wd[6];
#pragma unroll
    for (int r = 0; r < 6; r++) wd[r] = Wd[r*768 + d4];
    float bd = bde[d4];

    float An[NST];
#pragma unroll
    for (int n = 0; n < NST; n++) An[n] = g_A[d4*NST + n];
    bool sA = a_structured(An);
    bool fwd = d4 < 384;
    int du = d4 % 192;
    float dp = Dp[d4];

    size_t idx0 = ((size_t)(b*NCH + c)*768 + d4)*NST;
    const float4* H4 = (const float4*)(g_chH + idx0);
    float h[NST];
#pragma unroll
    for (int k = 0; k < 4; k++) {
        float4 hv = H4[k];
        h[4*k] = hv.x; h[4*k+1] = hv.y; h[4*k+2] = hv.z; h[4*k+3] = hv.w;
    }

    if (sA) {
        for (int i = 0; i < CLEN; i++) {
            const float* row = sXD + i*40;
            float a0 = bd;
#pragma unroll
            for (int r = 0; r < 6; r++) a0 = fmaf(row[r], wd[r], a0);
            float dl = softplusf(a0);
            int l = l0 + i;
            int lu = fwd ? l : (LL-1-l);
            float u = g_xc[(size_t)(b*LL + lu)*192 + du];
            float s = dl*u;
            float e1 = __expf(dl*An[0]);
            float a = e1;
            const float* bn = row + 8;
            const float* cn = row + 24;
            float y = dp*u;
#pragma unroll
            for (int n = 0; n < NST; n++) {
                h[n] = fmaf(a, h[n], s*bn[n]);
                y = fmaf(h[n], cn[n], y);
                a *= e1;
            }
            g_y[(size_t)(b*LL + l)*768 + d4] = y;
        }
    } else {
        for (int i = 0; i < CLEN; i++) {
            const float* row = sXD + i*40;
            float a0 = bd;
#pragma unroll
            for (int r = 0; r < 6; r++) a0 = fmaf(row[r], wd[r], a0);
            float dl = softplusf(a0);
            int l = l0 + i;
            int lu = fwd ? l : (LL-1-l);
            float u = g_xc[(size_t)(b*LL + lu)*192 + du];
            float s = dl*u;
            const float* bn = row + 8;
            const float* cn = row + 24;
            float y = dp*u;
#pragma unroll
            for (int n = 0; n < NST; n++) {
                float a = __expf(dl*An[n]);
                h[n] = fmaf(a, h[n], s*bn[n]);
                y = fmaf(h[n], cn[n], y);
            }
            g_y[(size_t)(b*LL + l)*768 + d4] = y;
        }
    }
}

// ---------------- K5a: combine 4 dirs + LayerNorm + gate -> g_gT (d-major) ----------------
__global__ void k5a_gate(const float* __restrict__ ln_g, const float* __restrict__ ln_b) {
    __shared__ float sT[8][193];
    int tid = threadIdx.x;
    int warp = tid >> 5, lane = tid & 31;
    int b  = blockIdx.y;
    int p0 = blockIdx.x*8;
    int p  = p0 + warp;
    int pf = LL - 1 - p;
    const float* yr  = g_y + (size_t)(b*LL + p)*768;
    const float* yrf = g_y + (size_t)(b*LL + pf)*768;

    float v[6];
    float s1 = 0.f, s2 = 0.f;
#pragma unroll
    for (int k = 0; k < 6; k++) {
        int ch = lane + 32*k;
        float vv = yr[ch] + yr[192+ch] + yrf[384+ch] + yrf[576+ch];
        v[k] = vv;
        s1 += vv; s2 += vv*vv;
    }
#pragma unroll
    for (int off = 16; off >= 1; off >>= 1) {
        s1 += __shfl_xor_sync(0xffffffffu, s1, off);
        s2 += __shfl_xor_sync(0xffffffffu, s2, off);
    }
    float mu = s1 * (1.f/192.f);
    float var = s2 * (1.f/192.f) - mu*mu;
    float rstd = rsqrtf(var + 1e-5f);

    const float* zrow = g_xz + (size_t)(b*LL + p)*384 + 192;
#pragma unroll
    for (int k = 0; k < 6; k++) {
        int ch = lane + 32*k;
        float yn = (v[k] - mu)*rstd*ln_g[ch] + ln_b[ch];
        float z  = zrow[ch];
        sT[warp][ch] = yn * z / (1.f + __expf(-z));
    }
    __syncthreads();
    for (int i = tid; i < 192*8; i += 256) {
        int ch = i >> 3, pp = i & 7;
        g_gT[(size_t)(b*192 + ch)*LL + p0 + pp] = sT[pp][ch];
    }
}

// ---------------- K5b: out GEMM (192 -> 96), reads d-major g_gT ----------------
// 256 threads, tile 64 pixels; thread: 8 px x 3 c-groups.
__global__ void k5b_out(const float* __restrict__ W_out, float* __restrict__ out) {
    __shared__ float sG[32*68];
    __shared__ float sW[32*96];
    int tid = threadIdx.x;
    int b  = blockIdx.y;
    int l0 = blockIdx.x*64;
    int eg = tid & 31;
    int jq = tid >> 5;       // 0..7, 8 pixels each
    float acc[3][8];
#pragma unroll
    for (int e = 0; e < 3; e++)
#pragma unroll
        for (int p = 0; p < 8; p++) acc[e][p] = 0.f;

    for (int k0 = 0; k0 < 192; k0 += 32) {
        __syncthreads();
        for (int i = tid; i < 32*64; i += 256) {
            int dd = i >> 6, pix = i & 63;
            sG[dd*68 + pix] = g_gT[(size_t)(b*192 + k0 + dd)*LL + l0 + pix];
        }
        for (int i = tid; i < 32*96; i += 256)
            sW[i] = W_out[k0*96 + i];
        __syncthreads();
#pragma unroll 4
        for (int dd = 0; dd < 32; dd++) {
            float4 xa = *(const float4*)(sG + dd*68 + jq*8);
            float4 xb = *(const float4*)(sG + dd*68 + jq*8 + 4);
            float xs[8] = {xa.x,xa.y,xa.z,xa.w,xb.x,xb.y,xb.z,xb.w};
            float w0 = sW[dd*96 + eg];
            float w1 = sW[dd*96 + 32 + eg];
            float w2 = sW[dd*96 + 64 + eg];
#pragma unroll
            for (int p = 0; p < 8; p++) {
                acc[0][p] = fmaf(xs[p], w0, acc[0][p]);
                acc[1][p] = fmaf(xs[p], w1, acc[1][p]);
                acc[2][p] = fmaf(xs[p], w2, acc[2][p]);
            }
        }
    }
#pragma unroll
    for (int e = 0; e < 3; e++) {
        int cc = e*32 + eg;
        float* op = out + (size_t)(b*96 + cc)*LL + l0 + jq*8;
        float4 o0 = make_float4(acc[e][0],acc[e][1],acc[e][2],acc[e][3]);
        float4 o1 = make_float4(acc[e][4],acc[e][5],acc[e][6],acc[e][7]);
        *(float4*)(op)     = o0;
        *(float4*)(op + 4) = o1;
    }
}

// ---------------- launch ----------------
extern "C" void kernel_launch(void* const* d_in, const int* in_sizes, int n_in,
                              void* d_out, int out_size) {
    const float* x       = (const float*)d_in[0];
    const float* W_in    = (const float*)d_in[1];
    const float* b_in    = (const float*)d_in[2];
    const float* w_dw    = (const float*)d_in[3];
    const float* b_dw    = (const float*)d_in[4];
    const float* A_log   = (const float*)d_in[5];
    const float* Dp      = (const float*)d_in[6];
    const float* W_x     = (const float*)d_in[7];
    const float* W_delta = (const float*)d_in[8];
    const float* b_delta = (const float*)d_in[9];
    const float* ln_g    = (const float*)d_in[10];
    const float* ln_b    = (const float*)d_in[11];
    const float* W_out   = (const float*)d_in[12];
    float* out = (float*)d_out;

    k_prep<<<48, 256>>>(A_log, W_x);
    k1_inproj<<<dim3(LL/64, BB), 512>>>(x, W_in, b_in);
    k2_conv<<<(BB*LL*192)/256, 256>>>(w_dw, b_dw);
    k3a_xdbl<<<dim3(72, 2, BB), 256>>>();
    k3s_sum<<<(BB*LL*40 + 255)/256, 256>>>();
    k4a_scanA<<<dim3(6, NCH, BB), 128>>>(W_delta, b_delta);
    k4b_prefix<<<(BB*768*16)/256, 256>>>();
    k4c_scanC<<<dim3(6, NCH, BB), 128>>>(Dp, W_delta, b_delta);
    k5a_gate<<<dim3(LL/8, BB), 256>>>(ln_g, ln_b);
    k5b_out<<<dim3(LL/64, BB), 256>>>(W_out, out);
}